// round 17
// baseline (speedup 1.0000x reference)
#include <cuda_runtime.h>
#include <cstdint>
#include <math.h>

#define IN_D  64
#define H_D   256
#define B_D   128
#define T_D   512
#define GRID  128
#define BLOCK 512

typedef unsigned long long u64;

// ---------------- device globals ----------------
__device__ float h1_buf[2][B_D * H_D];
__device__ float h2_buf[2][B_D * H_D];
__device__ unsigned bar_cnt[4][2][32];   // [bgroup][half] monotone counters, padded lines

// ---------------- smem layout ----------------
// wA : [32 c][162 k2] u64 = 41472  (layer1, K=320, k-order = [h1(256)|x(64)])
// wB : [32 c][258 k2] u64 = 66048  (layer2, K=512, k-order = [h1(256)|h2(256)])
// u  : [32 b][129 f4]     = 66048  per-half rows: 0..63 h1 (persist), 64..79 x / 64..127 h2
// part: [8 sl][16 b][40 c] f32 = 20480  (shared by all 4 sub-phases, sync-separated)
// gate: [16][32] f32 = 2048
#define WA_S2 81
#define WB_S2 129
#define OFF_WA 0
#define OFF_WB 41472
#define OFF_U  107520
#define OFF_P  173568
#define OFF_G  194048
#define OFF_BA 196096
#define OFF_BB 196224
#define SMEM_BYTES 196352

// ---------------- asm helpers ----------------
__device__ __forceinline__ unsigned ld_acq(const unsigned* p) {
    unsigned v;
    asm volatile("ld.acquire.gpu.u32 %0, [%1];" : "=r"(v) : "l"(p) : "memory");
    return v;
}
__device__ __forceinline__ void red_rel_add1(unsigned* p) {
    asm volatile("red.release.gpu.global.add.u32 [%0], 1;" :: "l"(p) : "memory");
}
__device__ __forceinline__ u64 fma2(u64 a, u64 b, u64 c) {
    u64 d;
    asm("fma.rn.f32x2 %0, %1, %2, %3;" : "=l"(d) : "l"(a), "l"(b), "l"(c));
    return d;
}
__device__ __forceinline__ float2 unpack2(u64 v) {
    float2 r; asm("mov.b64 {%0,%1}, %2;" : "=f"(r.x), "=f"(r.y) : "l"(v)); return r;
}
__device__ __forceinline__ float tanh_fast(float x) {
    float r;
    asm("tanh.approx.f32 %0, %1;" : "=f"(r) : "f"(x));
    return r;
}

// ---------------- half-batch register-tiled GEMM ----------------
// 16 warps = 8 k-slices(sl) x 2 c-halves(cg). Lanes (bq 0..7, cq 0..3).
// Thread tile 2b x 4c: b = hbase + bq + 8r, c = cg*16 + 2cq + {0,1,8,9}.
template<int K2S, int WS2>
__device__ __forceinline__ void gemm_half(const u64* __restrict__ wsm,
                                          const u64* __restrict__ usm,
                                          float* __restrict__ part,
                                          int sl, int cg, int lane, int hbase) {
    const int bq = lane & 7, cq = (lane >> 3) & 3;
    const int k2h = (sl * K2S) >> 1;
    const ulonglong2* up = (const ulonglong2*)usm + (hbase + bq) * WB_S2 + k2h;
    const ulonglong2* wp = (const ulonglong2*)wsm + (cg * 16 + 2 * cq) * WS2 + k2h;

    u64 acc[2][4];
#pragma unroll
    for (int r = 0; r < 2; ++r)
#pragma unroll
        for (int j = 0; j < 4; ++j) acc[r][j] = 0;

#pragma unroll 2
    for (int k = 0; k < K2S / 2; ++k) {
        ulonglong2 uf0 = up[k];
        ulonglong2 uf1 = up[k + 8 * WB_S2];
        ulonglong2 wf0 = wp[k];
        ulonglong2 wf1 = wp[k + WS2];
        ulonglong2 wf2 = wp[k + 8 * WS2];
        ulonglong2 wf3 = wp[k + 9 * WS2];
#pragma unroll
        for (int r = 0; r < 2; ++r) {
            ulonglong2 uv = r ? uf1 : uf0;
            acc[r][0] = fma2(uv.x, wf0.x, acc[r][0]);
            acc[r][0] = fma2(uv.y, wf0.y, acc[r][0]);
            acc[r][1] = fma2(uv.x, wf1.x, acc[r][1]);
            acc[r][1] = fma2(uv.y, wf1.y, acc[r][1]);
            acc[r][2] = fma2(uv.x, wf2.x, acc[r][2]);
            acc[r][2] = fma2(uv.y, wf2.y, acc[r][2]);
            acc[r][3] = fma2(uv.x, wf3.x, acc[r][3]);
            acc[r][3] = fma2(uv.y, wf3.y, acc[r][3]);
        }
    }

    float* pp = part + sl * 640 + bq * 40 + cg * 16 + 2 * cq;
#pragma unroll
    for (int r = 0; r < 2; ++r) {
        float2 a = unpack2(acc[r][0]);
        float2 b = unpack2(acc[r][1]);
        float2 c = unpack2(acc[r][2]);
        float2 d = unpack2(acc[r][3]);
        *(float2*)(pp + 320 * r)     = make_float2(a.x + a.y, b.x + b.y);
        *(float2*)(pp + 320 * r + 8) = make_float2(c.x + c.y, d.x + d.y);
    }
}

// reduce 8 slice-partials + bias -> gate[16][32]  (512 threads, 1 entry each)
__device__ __forceinline__ void reduce_half(const float* __restrict__ part,
                                            const float* __restrict__ bias,
                                            float* __restrict__ gate, int tid) {
    int b = tid >> 5, c = tid & 31;
    const float* p = part + b * 40 + c;
    float s = bias[c];
#pragma unroll
    for (int sl = 0; sl < 8; ++sl) s += p[sl * 640];
    gate[b * 32 + c] = s;
}

// ---------------- sLSTM cell elementwise update (gate indexed by local b) ----------------
__device__ __forceinline__ float cell_update(const float* __restrict__ gate,
                                             int bl, int je,
                                             float& c, float& m, float& n) {
    float ig = gate[bl * 32 +      je];
    float fg = gate[bl * 32 +  8 + je];
    float zg = gate[bl * 32 + 16 + je];
    float og = gate[bl * 32 + 24 + je];
    float z  = tanh_fast(zg);
    float o  = __fdividef(1.0f, 1.0f + __expf(-og));
    float mt = fmaxf(fg + m, ig);
    float it = __expf(ig - mt);
    float ft = __expf(fg + m - mt);
    c = ft * c + it * z;
    n = ft * n + it;
    m = mt;
    return o * __fdividef(c, n);
}

// ---------------- main persistent kernel ----------------
__global__ void __launch_bounds__(BLOCK, 1)
slstm_kernel(const float* __restrict__ x,
             const float* __restrict__ Wxh1, const float* __restrict__ bxh1,
             const float* __restrict__ Whh1, const float* __restrict__ bhh1,
             const float* __restrict__ Wxh2, const float* __restrict__ bxh2,
             const float* __restrict__ Whh2, const float* __restrict__ bhh2,
             const float* __restrict__ W1, const float* __restrict__ b1,
             const float* __restrict__ W2, const float* __restrict__ b2,
             const float* __restrict__ W3, const float* __restrict__ b3,
             float* __restrict__ out) {
    extern __shared__ char smem[];
    u64*    wA    = (u64*)(smem + OFF_WA);
    u64*    wB    = (u64*)(smem + OFF_WB);
    u64*    usm   = (u64*)(smem + OFF_U);
    float4* u4f   = (float4*)(smem + OFF_U);
    float*  part  = (float*)(smem + OFF_P);
    float*  gate  = (float*)(smem + OFF_G);
    float*  biasA = (float*)(smem + OFF_BA);
    float*  biasB = (float*)(smem + OFF_BB);

    const int tid  = threadIdx.x;
    const int warp = tid >> 5, lane = tid & 31;
    const int sl = warp >> 1, cg = warp & 1;
    const int bgroup = blockIdx.x >> 5;
    const int jgroup = blockIdx.x & 31;

    unsigned* cnt0 = &bar_cnt[bgroup][0][0];
    unsigned* cnt1 = &bar_cnt[bgroup][1][0];
    const unsigned base0 = ld_acq(cnt0);
    const unsigned base1 = ld_acq(cnt1);

    // x staging identity: thread -> (half hx, local row bx, quad sq)
    const int hx = tid >> 8, bx = (tid >> 4) & 15, sq = tid & 15;
    const int bglob_x = bgroup * 32 + hx * 16 + bx;
    const float4 zero4 = make_float4(0.f, 0.f, 0.f, 0.f);

    // prefetch x(0)
    float4 xv = *(const float4*)(x + (bglob_x * T_D + 0) * IN_D + sq * 4);

    // ---- stage weights + biases; zero u h1 rows ----
    {
        float2* wAf = (float2*)wA;
        for (int s = tid; s < 32 * 160; s += BLOCK) {
            int c = s / 160, k2 = s - c * 160;
            int col = (c >> 3) * 256 + jgroup * 8 + (c & 7);
            int k0 = 2 * k2;
            float2 v;
            if (k0 < H_D) v = *(const float2*)(Whh1 + col * H_D + k0);
            else          v = *(const float2*)(Wxh1 + col * IN_D + (k0 - H_D));
            wAf[c * 162 + k2] = v;
        }
        float2* wBf = (float2*)wB;
        for (int s = tid; s < 32 * 256; s += BLOCK) {
            int c = s >> 8, k2 = s & 255;
            int col = (c >> 3) * 256 + jgroup * 8 + (c & 7);
            int k0 = 2 * k2;
            float2 v;
            if (k0 < H_D) v = *(const float2*)(Wxh2 + col * H_D + k0);
            else          v = *(const float2*)(Whh2 + col * H_D + (k0 - H_D));
            wBf[c * 258 + k2] = v;
        }
        for (int s = tid; s < 32 * 64; s += BLOCK) {
            int b = s >> 6, q = s & 63;
            u4f[b * 129 + q] = zero4;
        }
    }
    if (tid < 32) {
        int col = (tid >> 3) * 256 + jgroup * 8 + (tid & 7);
        biasA[tid] = bxh1[col] + bhh1[col];
        biasB[tid] = bxh2[col] + bhh2[col];
    }
    __syncthreads();

    // per-thread cell state (tid<256): be = tid>>3 in 0..31, je = tid&7
    float c1 = 0.f, m1 = 0.f, n1 = 0.f;
    float c2 = 0.f, m2 = 0.f, n2 = 0.f;
    const int be = tid >> 3, je = tid & 7;
    const int bl = be & 15;                 // local b within half
    const int cell_h = (tid >> 7);          // half this cell thread belongs to (valid tid<256)
    const int bglob_e = bgroup * 32 + be;
    const int jglob   = jgroup * 8 + je;

    for (int t = 0; t < T_D; ++t) {
        float*       h1cur = h1_buf[t & 1];
        float*       h2cur = h2_buf[t & 1];
        const float* h2old = h2_buf[(t + 1) & 1];

        // ================= phase A, both halves (arrive-only barriers) =================
#pragma unroll
        for (int h = 0; h < 2; ++h) {
            // stage x into rows 64..79 of this half; prefetch next x
            if (hx == h) {
                u4f[(h * 16 + bx) * 129 + 64 + sq] = xv;
                if (t + 1 < T_D)
                    xv = *(const float4*)(x + (bglob_x * T_D + (t + 1)) * IN_D + sq * 4);
            }
            __syncthreads();

            gemm_half<20, WA_S2>(wA, usm, part, sl, cg, lane, h * 16);
            __syncthreads();

            reduce_half(part, biasA, gate, tid);
            __syncthreads();

            if (tid < 256 && cell_h == h) {
                float h1v = cell_update(gate, bl, je, c1, m1, n1);
                h1cur[bglob_e * H_D + jglob] = h1v;
            }
            __syncthreads();                       // orders h1 stores before arrive
            if (tid == 0) red_rel_add1(h ? cnt1 : cnt0);
        }

        // ================= phase B, both halves (wait then compute) =================
#pragma unroll
        for (int h = 0; h < 2; ++h) {
            // wait bar(h): hidden under A-h1 (for h=0) / B-h0 (for h=1)
            if (tid == 0) {
                unsigned tgt = (h ? base1 : base0) + 32u * ((unsigned)t + 1u);
                unsigned* c = h ? cnt1 : cnt0;
                while ((int)(ld_acq(c) - tgt) < 0) { }
            }
            __syncthreads();

            // stage: h1(t) -> rows 0..63, h2(t-1) -> rows 64..127 of this half
            {
                float4 v[4];
#pragma unroll
                for (int k = 0; k < 4; ++k) {
                    int s = tid + 512 * k;
                    int b = s >> 7, q = s & 127;
                    int bg = bgroup * 32 + h * 16 + b;
                    if (q < 64)
                        v[k] = __ldcg((const float4*)(h1cur + bg * H_D + q * 4));
                    else
                        v[k] = (t == 0) ? zero4
                             : __ldcg((const float4*)(h2old + bg * H_D + (q - 64) * 4));
                }
#pragma unroll
                for (int k = 0; k < 4; ++k) {
                    int s = tid + 512 * k;
                    int b = s >> 7, q = s & 127;
                    u4f[(h * 16 + b) * 129 + q] = v[k];
                }
            }
            __syncthreads();

            gemm_half<32, WB_S2>(wB, usm, part, sl, cg, lane, h * 16);
            __syncthreads();

            reduce_half(part, biasB, gate, tid);
            __syncthreads();

            if (tid < 256 && cell_h == h) {
                float h2v = cell_update(gate, bl, je, c2, m2, n2);
                h2cur[bglob_e * H_D + jglob] = h2v;
            }
            // no trailing sync: next phase's wait-sync / stage-sync provides ordering
        }
    }

    // final bgroup barrier: order peers' cellB(T-1) before head-MLP reads (own bgroup only)
    __syncthreads();
    if (tid == 0) {
        red_rel_add1(cnt0);
        unsigned tgt = base0 + 32u * ((unsigned)T_D + 1u);
        while ((int)(ld_acq(cnt0) - tgt) < 0) { }
    }
    __syncthreads();

    // ---- head MLP: one batch row per CTA (reads own-bgroup h2 rows) ----
    {
        const float* h2fin = h2_buf[(T_D - 1) & 1];
        int b = blockIdx.x;
        float* hb = (float*)(smem + OFF_U);
        float* o1 = hb + 256;
        float* o2 = o1 + 128;
        float* pr = o2 + 64;
        for (int i = tid; i < H_D; i += BLOCK) hb[i] = __ldcg(h2fin + b * H_D + i);
        __syncthreads();
        if (tid < 128) {
            const float* w = W1 + tid * H_D;
            float s = b1[tid];
#pragma unroll 4
            for (int k = 0; k < H_D; k += 4) {
                float4 hv = *(const float4*)(hb + k);
                float4 wv = *(const float4*)(w + k);
                s += hv.x * wv.x + hv.y * wv.y + hv.z * wv.z + hv.w * wv.w;
            }
            o1[tid] = fmaxf(s, 0.f);
        }
        __syncthreads();
        if (tid < 64) {
            const float* w = W2 + tid * 128;
            float s = b2[tid];
#pragma unroll 4
            for (int k = 0; k < 128; ++k) s += o1[k] * w[k];
            o2[tid] = fmaxf(s, 0.f);
        }
        __syncthreads();
        if (tid < 64) pr[tid] = o2[tid] * W3[tid];
        __syncthreads();
        if (tid == 0) {
            float s = b3[0];
            for (int k = 0; k < 64; ++k) s += pr[k];
            out[b] = s;
        }
    }
}

extern "C" void kernel_launch(void* const* d_in, const int* in_sizes, int n_in,
                              void* d_out, int out_size) {
    const float* x    = (const float*)d_in[0];
    const float* Wxh1 = (const float*)d_in[1];
    const float* bxh1 = (const float*)d_in[2];
    const float* Whh1 = (const float*)d_in[3];
    const float* bhh1 = (const float*)d_in[4];
    const float* Wxh2 = (const float*)d_in[5];
    const float* bxh2 = (const float*)d_in[6];
    const float* Whh2 = (const float*)d_in[7];
    const float* bhh2 = (const float*)d_in[8];
    const float* W1   = (const float*)d_in[9];
    const float* b1   = (const float*)d_in[10];
    const float* W2   = (const float*)d_in[11];
    const float* b2   = (const float*)d_in[12];
    const float* W3   = (const float*)d_in[13];
    const float* b3   = (const float*)d_in[14];

    cudaFuncSetAttribute(slstm_kernel,
                         cudaFuncAttributeMaxDynamicSharedMemorySize, SMEM_BYTES);
    slstm_kernel<<<GRID, BLOCK, SMEM_BYTES>>>(x, Wxh1, bxh1, Whh1, bhh1,
                                              Wxh2, bxh2, Whh2, bhh2,
                                              W1, b1, W2, b2, W3, b3,
                                              (float*)d_out);
}